// round 5
// baseline (speedup 1.0000x reference)
#include <cuda_runtime.h>
#include <cuda_bf16.h>
#include <cstring>
#include <cstdint>

#define NN 50000
#define EE 400000
#define NHEAD 8
#define DEF 16
#define DNF 16

// ---------------- device global scratch ------------------------------------
__device__ float g_N1t[128 * 128];   // (W1@W_ni)^T: [k][c]
__device__ float g_A2t[128 * 128];   // (W2@W_fij)^T
__device__ float g_N3t[128 * 128];   // (W3@W_nj)^T
__device__ float g_Wnt[128 * 128];   // W_node^T
__device__ float g_wsum[DEF];
// B operands as bf16 [n][k], row stride 136 elements
__device__ __nv_bfloat16 g_Bhi[4 * 128 * 136];
__device__ __nv_bfloat16 g_Blo[4 * 128 * 136];
__device__ float g_tsrc[NN * 128];
__device__ float g_tdst[NN * 128];
__device__ float g_hnode[NN * 128];
__device__ float g_a[EE * NHEAD];    // exp(logit) * norm
__device__ float g_den[NN * NHEAD];  // sum of raw exp(logit)

// ---------------- smem layout (bytes) ---------------------------------------
#define RSTRIDE 272                 // 136 bf16 per row
#define TILE_M  64
#define A_BYTES (TILE_M * RSTRIDE)  // 17408
#define B_BYTES (128 * RSTRIDE)     // 34816
#define SM_BIAS 0
#define SM_WS   512
#define SM_A    1024
#define SM_AHI  SM_A
#define SM_ALO  (SM_A + A_BYTES)        // 18432
#define SM_BHI  (SM_ALO + A_BYTES)      // 35840
#define SM_BLO  (SM_BHI + B_BYTES)      // 70656
#define SM_TOTAL (SM_BLO + B_BYTES)     // 105472
#define SM_FBUF SM_A                    // fp32 staging overlays A hi+lo (33792 <= 34816)
#define FB_STRIDE 132

// ---------------- small kernels ----------------------------------------------
__global__ void k_init(float* __restrict__ out1) {
    int i = blockIdx.x * blockDim.x + threadIdx.x;
    if (i < NN * NHEAD) g_den[i] = 0.f;
    if (i < NN * DNF)   out1[i] = 0.f;
}

__global__ void k_weights(const float* __restrict__ W_edges,
                          const float* __restrict__ W_ni,
                          const float* __restrict__ W_nj,
                          const float* __restrict__ W_fij,
                          const float* __restrict__ W_node,
                          const float* __restrict__ W_attn) {
    int k = blockIdx.x, c = threadIdx.x, m = blockIdx.y;
    if (m == 0) {
        float acc = 0.f;
        for (int j = 0; j < 128; ++j) acc += W_edges[c * 384 + j] * W_ni[j * 128 + k];
        g_N1t[k * 128 + c] = acc;
    } else if (m == 1) {
        float acc = 0.f;
        for (int j = 0; j < 128; ++j) acc += W_edges[c * 384 + 128 + j] * W_fij[j * 128 + k];
        g_A2t[k * 128 + c] = acc;
    } else if (m == 2) {
        float acc = 0.f;
        for (int j = 0; j < 128; ++j) acc += W_edges[c * 384 + 256 + j] * W_nj[j * 128 + k];
        g_N3t[k * 128 + c] = acc;
    } else {
        g_Wnt[k * 128 + c] = W_node[c * 128 + k];
        if (k == 0 && c < DEF) {
            float s = 0.f;
            for (int h = 0; h < NHEAD; ++h) s += W_attn[h * DEF + c];
            g_wsum[c] = s;
        }
    }
}

// convert combined weights into bf16 hi/lo [n][k] stride-136 operands
__global__ void k_wconv() {
    int idx = blockIdx.x * blockDim.x + threadIdx.x;  // 65536
    int m = idx >> 14, r = idx & 16383;
    int n = r >> 7, k = r & 127;                      // B[n][k] = Wt[k][n]
    const float* srcs[4] = {g_N1t, g_A2t, g_N3t, g_Wnt};
    float w = srcs[m][k * 128 + n];
    __nv_bfloat16 h = __float2bfloat16(w);
    __nv_bfloat16 l = __float2bfloat16(w - __bfloat162float(h));
    g_Bhi[m * 128 * 136 + n * 136 + k] = h;
    g_Blo[m * 128 * 136 + n * 136 + k] = l;
}

// ---------------- fp32 -> bf16 hi/lo tile stage ------------------------------
__device__ __forceinline__ void split8(const float4 v0, const float4 v1, uint4& H, uint4& L) {
    float x[8] = {v0.x, v0.y, v0.z, v0.w, v1.x, v1.y, v1.z, v1.w};
    unsigned hu[4], lu[4];
#pragma unroll
    for (int j = 0; j < 4; ++j) {
        __nv_bfloat162 hp = __floats2bfloat162_rn(x[2 * j], x[2 * j + 1]);
        float ra = x[2 * j]     - __low2float(hp);
        float rb = x[2 * j + 1] - __high2float(hp);
        __nv_bfloat162 lp = __floats2bfloat162_rn(ra, rb);
        memcpy(&hu[j], &hp, 4);
        memcpy(&lu[j], &lp, 4);
    }
    H = make_uint4(hu[0], hu[1], hu[2], hu[3]);
    L = make_uint4(lu[0], lu[1], lu[2], lu[3]);
}

// stage TILE_M x 128 fp32 rows into bf16 hi/lo smem
__device__ __forceinline__ void load_tile(char* smc, const float* __restrict__ srcp,
                                          int base, int limit, int t) {
    for (int i = t; i < TILE_M * 16; i += 256) {
        int row = i >> 4, col = (i & 15) * 8;
        int gr = base + row;
        float4 v0, v1;
        if (gr < limit) {
            v0 = __ldg((const float4*)(srcp + (size_t)gr * 128 + col));
            v1 = __ldg((const float4*)(srcp + (size_t)gr * 128 + col + 4));
        } else {
            v0 = make_float4(0.f, 0.f, 0.f, 0.f); v1 = v0;
        }
        uint4 H, L;
        split8(v0, v1, H, L);
        *(uint4*)(smc + SM_AHI + row * RSTRIDE + col * 2) = H;
        *(uint4*)(smc + SM_ALO + row * RSTRIDE + col * 2) = L;
    }
}

// ---------------- mma.sync bf16 split GEMM core ------------------------------
__device__ __forceinline__ void mma16816(float (&d)[4], const uint32_t (&a)[4],
                                         const uint32_t (&b)[2]) {
    asm("mma.sync.aligned.m16n8k16.row.col.f32.bf16.bf16.f32 "
        "{%0,%1,%2,%3}, {%4,%5,%6,%7}, {%8,%9}, {%0,%1,%2,%3};"
        : "+f"(d[0]), "+f"(d[1]), "+f"(d[2]), "+f"(d[3])
        : "r"(a[0]), "r"(a[1]), "r"(a[2]), "r"(a[3]), "r"(b[0]), "r"(b[1]));
}

__device__ __forceinline__ uint32_t lds32(const char* base, int r, int k) {
    return *(const uint32_t*)(base + r * RSTRIDE + k * 2);
}

// block tile 64x128, warp tile 32x32; acc[mt][nt][4]
__device__ __forceinline__ void mm_split(char* smc, int warp, int lane,
                                         float (&acc)[2][4][4]) {
    int warpm = warp & 1, warpn = warp >> 1;
    int q = lane >> 2, tid = lane & 3;
    const char* Ahi = smc + SM_AHI;
    const char* Alo = smc + SM_ALO;
    const char* Bhi = smc + SM_BHI;
    const char* Blo = smc + SM_BLO;

#pragma unroll
    for (int mt = 0; mt < 2; ++mt)
#pragma unroll
        for (int nt = 0; nt < 4; ++nt)
#pragma unroll
            for (int j = 0; j < 4; ++j) acc[mt][nt][j] = 0.f;

#pragma unroll
    for (int k0 = 0; k0 < 8; ++k0) {
        int kk = k0 * 16 + 2 * tid;
        uint32_t ahi[2][4], alo[2][4], bhi[4][2], blo[4][2];
#pragma unroll
        for (int mt = 0; mt < 2; ++mt) {
            int r = warpm * 32 + mt * 16 + q;
            ahi[mt][0] = lds32(Ahi, r, kk);
            ahi[mt][1] = lds32(Ahi, r + 8, kk);
            ahi[mt][2] = lds32(Ahi, r, kk + 8);
            ahi[mt][3] = lds32(Ahi, r + 8, kk + 8);
            alo[mt][0] = lds32(Alo, r, kk);
            alo[mt][1] = lds32(Alo, r + 8, kk);
            alo[mt][2] = lds32(Alo, r, kk + 8);
            alo[mt][3] = lds32(Alo, r + 8, kk + 8);
        }
#pragma unroll
        for (int nt = 0; nt < 4; ++nt) {
            int n = warpn * 32 + nt * 8 + q;
            bhi[nt][0] = lds32(Bhi, n, kk);
            bhi[nt][1] = lds32(Bhi, n, kk + 8);
            blo[nt][0] = lds32(Blo, n, kk);
            blo[nt][1] = lds32(Blo, n, kk + 8);
        }
#pragma unroll
        for (int mt = 0; mt < 2; ++mt)
#pragma unroll
            for (int nt = 0; nt < 4; ++nt) mma16816(acc[mt][nt], ahi[mt], bhi[nt]);
#pragma unroll
        for (int mt = 0; mt < 2; ++mt)
#pragma unroll
            for (int nt = 0; nt < 4; ++nt) mma16816(acc[mt][nt], ahi[mt], blo[nt]);
#pragma unroll
        for (int mt = 0; mt < 2; ++mt)
#pragma unroll
            for (int nt = 0; nt < 4; ++nt) mma16816(acc[mt][nt], alo[mt], bhi[nt]);
    }
}

__device__ __forceinline__ void dump_acc(char* smc, int warp, int lane,
                                         const float (&acc)[2][4][4]) {
    int warpm = warp & 1, warpn = warp >> 1;
    int q = lane >> 2, tid = lane & 3;
    float* fb = (float*)(smc + SM_FBUF);
#pragma unroll
    for (int mt = 0; mt < 2; ++mt) {
        int r = warpm * 32 + mt * 16 + q;
#pragma unroll
        for (int nt = 0; nt < 4; ++nt) {
            int c = warpn * 32 + nt * 8 + 2 * tid;
            *(float2*)&fb[r * FB_STRIDE + c]       = make_float2(acc[mt][nt][0], acc[mt][nt][1]);
            *(float2*)&fb[(r + 8) * FB_STRIDE + c] = make_float2(acc[mt][nt][2], acc[mt][nt][3]);
        }
    }
}

// ---------------- node GEMMs -------------------------------------------------
__global__ void __launch_bounds__(256, 2)
k_node_mma(const float* __restrict__ nfeats, const float* __restrict__ b_node) {
    extern __shared__ char smc[];
    int t = threadIdx.x, warp = t >> 5, lane = t & 31;
    int m = blockIdx.y;
    int mat = (m == 0) ? 0 : (m == 1 ? 2 : 3);
    float* OUT = (m == 0) ? g_tsrc : (m == 1 ? g_tdst : g_hnode);

    const uint4* bh = (const uint4*)(g_Bhi + mat * 128 * 136);
    const uint4* bl = (const uint4*)(g_Blo + mat * 128 * 136);
    for (int i = t; i < 2176; i += 256) {
        ((uint4*)(smc + SM_BHI))[i] = bh[i];
        ((uint4*)(smc + SM_BLO))[i] = bl[i];
    }
    float* bias_s = (float*)(smc + SM_BIAS);
    for (int i = t; i < 128; i += 256) bias_s[i] = (m == 2) ? __ldg(&b_node[i]) : 0.f;

    int ntiles = (NN + TILE_M - 1) / TILE_M;   // 782
    for (int tile = blockIdx.x; tile < ntiles; tile += gridDim.x) {
        int n0 = tile * TILE_M;
        load_tile(smc, nfeats, n0, NN, t);
        __syncthreads();
        float acc[2][4][4];
        mm_split(smc, warp, lane, acc);
        __syncthreads();        // all LDS reads of A done before fbuf overlay
        dump_acc(smc, warp, lane, acc);
        __syncthreads();
        // epilogue: 4 threads per row, 32 cols each
        int n = n0 + (t >> 2);
        if (n < NN) {
            int c0 = (t & 3) * 32;
            const float* frow = (float*)(smc + SM_FBUF) + (t >> 2) * FB_STRIDE + c0;
            float* op = OUT + (size_t)n * 128 + c0;
#pragma unroll
            for (int j = 0; j < 8; ++j) {
                float4 v = *(const float4*)(frow + j * 4);
                v.x += bias_s[c0 + j * 4];
                v.y += bias_s[c0 + j * 4 + 1];
                v.z += bias_s[c0 + j * 4 + 2];
                v.w += bias_s[c0 + j * 4 + 3];
                ((float4*)op)[j] = v;
            }
        }
        __syncthreads();        // epilogue reads done before next load_tile
    }
}

// ---------------- fused edge kernel ------------------------------------------
__global__ void __launch_bounds__(256, 2)
k_edge_mma(const float* __restrict__ efeats, const int* __restrict__ src,
           const int* __restrict__ dst, const float* __restrict__ norm,
           const float* __restrict__ bias, float* __restrict__ out2) {
    extern __shared__ char smc[];
    int t = threadIdx.x, warp = t >> 5, lane = t & 31;

    const uint4* bh = (const uint4*)(g_Bhi + 1 * 128 * 136);
    const uint4* bl = (const uint4*)(g_Blo + 1 * 128 * 136);
    for (int i = t; i < 2176; i += 256) {
        ((uint4*)(smc + SM_BHI))[i] = bh[i];
        ((uint4*)(smc + SM_BLO))[i] = bl[i];
    }
    float* bias_s = (float*)(smc + SM_BIAS);
    float* ws_s   = (float*)(smc + SM_WS);
    for (int i = t; i < 128; i += 256) bias_s[i] = __ldg(&bias[i]);
    if (t < DEF) ws_s[t] = g_wsum[t];

    const int ntiles = EE / TILE_M;   // 6250 exact
    for (int tile = blockIdx.x; tile < ntiles; tile += gridDim.x) {
        int e0 = tile * TILE_M;
        load_tile(smc, efeats, e0, 0x7fffffff, t);
        __syncthreads();
        float acc[2][4][4];
        mm_split(smc, warp, lane, acc);
        __syncthreads();
        dump_acc(smc, warp, lane, acc);
        __syncthreads();

        // epilogue: 4 threads per edge row (quarters of 128 cols = 2 heads each)
        int e = e0 + (t >> 2);
        int quad = t & 3;
        int c0 = quad * 32;
        int s  = __ldg(&src[e]);
        int dd = __ldg(&dst[e]);
        float nrm = __ldg(&norm[e]);
        const float* frow = (float*)(smc + SM_FBUF) + (t >> 2) * FB_STRIDE + c0;
        const float4* tsp = (const float4*)(g_tsrc + (size_t)s * 128 + c0);
        const float4* tdp = (const float4*)(g_tdst + (size_t)dd * 128 + c0);

        float pd[16];
#pragma unroll
        for (int d = 0; d < 16; ++d) pd[d] = 0.f;
        float ex[2], exn[2];
#pragma unroll
        for (int hl = 0; hl < 2; ++hl) {
            float lgv = 0.f;
#pragma unroll
            for (int j = 0; j < 4; ++j) {
                float4 dv = *(const float4*)(frow + hl * 16 + j * 4);
                float4 a4 = __ldg(tsp + hl * 4 + j);
                float4 b4 = __ldg(tdp + hl * 4 + j);
                int cb = c0 + hl * 16 + j * 4;
                float v0 = dv.x + a4.x + b4.x;
                float v1 = dv.y + a4.y + b4.y;
                float v2 = dv.z + a4.z + b4.z;
                float v3 = dv.w + a4.w + b4.w;
                v0 = (v0 > 0.f) ? v0 : 0.01f * v0;
                v1 = (v1 > 0.f) ? v1 : 0.01f * v1;
                v2 = (v2 > 0.f) ? v2 : 0.01f * v2;
                v3 = (v3 > 0.f) ? v3 : 0.01f * v3;
                v0 += bias_s[cb];
                v1 += bias_s[cb + 1];
                v2 += bias_s[cb + 2];
                v3 += bias_s[cb + 3];
                pd[j * 4]     += v0;
                pd[j * 4 + 1] += v1;
                pd[j * 4 + 2] += v2;
                pd[j * 4 + 3] += v3;
                lgv += v0 * ws_s[j * 4] + v1 * ws_s[j * 4 + 1]
                     + v2 * ws_s[j * 4 + 2] + v3 * ws_s[j * 4 + 3];
            }
            ex[hl]  = __expf(lgv);
            exn[hl] = ex[hl] * nrm;
        }
        // combine head-sum partials across the quad
#pragma unroll
        for (int d = 0; d < 16; ++d) {
            pd[d] += __shfl_xor_sync(0xffffffffu, pd[d], 1);
            pd[d] += __shfl_xor_sync(0xffffffffu, pd[d], 2);
        }
        if (quad == 0) {
#pragma unroll
            for (int qj = 0; qj < 4; ++qj)
                ((float4*)(out2 + (size_t)e * DEF))[qj] =
                    make_float4(pd[qj * 4], pd[qj * 4 + 1], pd[qj * 4 + 2], pd[qj * 4 + 3]);
        }
        *(float2*)&g_a[(size_t)e * NHEAD + quad * 2] = make_float2(exn[0], exn[1]);
        atomicAdd(&g_den[(size_t)dd * NHEAD + quad * 2],     ex[0]);
        atomicAdd(&g_den[(size_t)dd * NHEAD + quad * 2 + 1], ex[1]);
        __syncthreads();
    }
}

// ---------------- message passing --------------------------------------------
__global__ void k_msg(const int* __restrict__ src, const int* __restrict__ dst,
                      float* __restrict__ out1) {
    int gid = blockIdx.x * blockDim.x + threadIdx.x;
    int e = gid >> 4, d = gid & 15;
    if (e >= EE) return;
    int s  = __ldg(&src[e]);
    int dd = __ldg(&dst[e]);
    float acc = 0.f;
#pragma unroll
    for (int h = 0; h < NHEAD; ++h) {
        float w = __fdividef(g_a[(size_t)e * NHEAD + h],
                             g_den[(size_t)dd * NHEAD + h]);
        acc += w * g_hnode[(size_t)s * 128 + h * DNF + d];
    }
    atomicAdd(&out1[(size_t)dd * DNF + d], acc);
}

// ---------------- launch ------------------------------------------------------
extern "C" void kernel_launch(void* const* d_in, const int* in_sizes, int n_in,
                              void* d_out, int out_size) {
    const float* nfeats  = (const float*)d_in[0];
    const float* efeats  = (const float*)d_in[1];
    const float* norm    = (const float*)d_in[2];
    const int*   src     = (const int*)d_in[3];
    const int*   dst     = (const int*)d_in[4];
    const float* W_ni    = (const float*)d_in[5];
    const float* W_nj    = (const float*)d_in[6];
    const float* W_fij   = (const float*)d_in[7];
    const float* W_edges = (const float*)d_in[8];
    const float* W_attn  = (const float*)d_in[9];
    const float* bias    = (const float*)d_in[10];
    const float* W_node  = (const float*)d_in[11];
    const float* b_node  = (const float*)d_in[12];

    float* out1 = (float*)d_out;
    float* out2 = out1 + (size_t)NN * DNF;

    cudaFuncSetAttribute(k_node_mma, cudaFuncAttributeMaxDynamicSharedMemorySize, SM_TOTAL);
    cudaFuncSetAttribute(k_edge_mma, cudaFuncAttributeMaxDynamicSharedMemorySize, SM_TOTAL);

    k_init<<<3125, 256>>>(out1);
    k_weights<<<dim3(128, 4), 128>>>(W_edges, W_ni, W_nj, W_fij, W_node, W_attn);
    k_wconv<<<256, 256>>>();
    k_node_mma<<<dim3(296, 3), 256, SM_TOTAL>>>(nfeats, b_node);
    k_edge_mma<<<296, 256, SM_TOTAL>>>(efeats, src, dst, norm, bias, out2);
    k_msg<<<(EE * DNF + 255) / 256, 256>>>(src, dst, out1);
}